// round 3
// baseline (speedup 1.0000x reference)
#include <cuda_runtime.h>

#define N_NODES 20000
#define DEG     16
#define IN_DIM  512
#define OUT_DIM 512
#define NHEAD   4
#define DH      128
#define D_ROPE  126

#define BM 128
#define BN 128
#define BK 16

// ---------------- scratch (static device globals: allocation-free) ----------
__device__ float g_q[N_NODES * OUT_DIM];
__device__ float g_k[N_NODES * OUT_DIM];
__device__ float g_v[N_NODES * OUT_DIM];
__device__ float g_y[N_NODES * OUT_DIM];
__device__ float g_WoP[OUT_DIM * OUT_DIM];

// ---------------- accurate sincos for |a| <~ 200 (fast-math safe) -----------
__device__ __forceinline__ void rope_sincos(float a, float& s_out, float& c_out) {
    // Cody-Waite reduction by pi/2 (split constants exact for |q| < 2^11)
    float j = rintf(a * 0.6366197723675814f);
    int   q = (int)j;
    float r = fmaf(j, -1.5703125f, a);
    r = fmaf(j, -4.837512969970703125e-4f, r);
    r = fmaf(j, -7.549789948768648e-8f, r);
    float r2 = r * r;
    // sin poly on [-pi/4, pi/4]
    float ss = -1.9515295891e-4f;
    ss = fmaf(ss, r2, 8.3321608736e-3f);
    ss = fmaf(ss, r2, -1.6666654611e-1f);
    ss = fmaf(ss * r2, r, r);
    // cos poly
    float cc = 2.443315711809948e-5f;
    cc = fmaf(cc, r2, -1.388731625493765e-3f);
    cc = fmaf(cc, r2, 4.166664568298827e-2f);
    cc = fmaf(cc, r2, -0.5f);
    cc = fmaf(cc, r2, 1.0f);
    int qq = q & 3;
    float sv = (qq & 1) ? cc : ss;
    float cv = (qq & 1) ? ss : cc;
    if (qq & 2)        sv = -sv;
    if ((qq + 1) & 2)  cv = -cv;
    s_out = sv; c_out = cv;
}

__device__ __forceinline__ float rope_inv_freq(int m) {
    // exp(-m * ln(10000)/21), matches jnp fp32 to ~1 ulp
    return expf(-0.43858763676075163f * (float)m);
}

// ---------------- permute Wo columns into head-major layout -----------------
// y is stored [n][h][d]; y_flat index in ref = d*4+h. WoP[o][j] = Wo[o][colmap(j)]
__global__ void permute_wo_kernel(const float* __restrict__ Wo) {
    int idx = blockIdx.x * 256 + threadIdx.x;          // 512*512 threads
    int o = idx >> 9;
    int j = idx & 511;
    g_WoP[idx] = Wo[o * 512 + ((j & 127) << 2) + (j >> 7)];
}

// ---------------- fused QKV GEMM (+bias, +q-scale, +RoPE) --------------------
// C[m, jg] = sum_k x[m,k] * W[perm(jg), k]; output layout [n][h][d] (jg = h*128+d)
__global__ __launch_bounds__(256, 2)
void qkv_gemm_kernel(const float* __restrict__ x, const float* __restrict__ pos,
                     const float* __restrict__ Wq, const float* __restrict__ bq,
                     const float* __restrict__ Wk, const float* __restrict__ bk,
                     const float* __restrict__ Wv, const float* __restrict__ bv)
{
    const int mode = blockIdx.z;  // 0=q, 1=k, 2=v
    const float* __restrict__ W    = (mode == 0) ? Wq : (mode == 1 ? Wk : Wv);
    const float* __restrict__ bias = (mode == 0) ? bq : (mode == 1 ? bk : bv);
    float* out = (mode == 0) ? g_q : (mode == 1 ? g_k : g_v);

    __shared__ float As[BK][BM + 4];
    __shared__ float Bs[BK][BN + 4];

    const int tid = threadIdx.x;
    const int m0 = blockIdx.x * BM;
    const int n0 = blockIdx.y * BN;

    const int lr = tid >> 2;           // 0..63
    const int lk = (tid & 3) << 2;     // 0,4,8,12

    const int gm0 = m0 + lr;
    const int gm1 = m0 + lr + 64;

    const int jg0 = n0 + lr;
    const int jg1 = n0 + lr + 64;
    const float* Wrow0 = W + (size_t)(((jg0 & 127) << 2) + (jg0 >> 7)) * IN_DIM;
    const float* Wrow1 = W + (size_t)(((jg1 & 127) << 2) + (jg1 >> 7)) * IN_DIM;

    const int ty = tid >> 4;   // 0..15 -> rows
    const int tx = tid & 15;   // 0..15 -> cols

    float acc[8][8];
#pragma unroll
    for (int i = 0; i < 8; i++)
#pragma unroll
        for (int j = 0; j < 8; j++) acc[i][j] = 0.f;

    for (int k0 = 0; k0 < IN_DIM; k0 += BK) {
        float4 a0 = (gm0 < N_NODES) ? *(const float4*)(x + (size_t)gm0 * IN_DIM + k0 + lk)
                                    : make_float4(0.f, 0.f, 0.f, 0.f);
        float4 a1 = (gm1 < N_NODES) ? *(const float4*)(x + (size_t)gm1 * IN_DIM + k0 + lk)
                                    : make_float4(0.f, 0.f, 0.f, 0.f);
        float4 b0 = *(const float4*)(Wrow0 + k0 + lk);
        float4 b1 = *(const float4*)(Wrow1 + k0 + lk);

        As[lk + 0][lr] = a0.x; As[lk + 1][lr] = a0.y;
        As[lk + 2][lr] = a0.z; As[lk + 3][lr] = a0.w;
        As[lk + 0][lr + 64] = a1.x; As[lk + 1][lr + 64] = a1.y;
        As[lk + 2][lr + 64] = a1.z; As[lk + 3][lr + 64] = a1.w;

        Bs[lk + 0][lr] = b0.x; Bs[lk + 1][lr] = b0.y;
        Bs[lk + 2][lr] = b0.z; Bs[lk + 3][lr] = b0.w;
        Bs[lk + 0][lr + 64] = b1.x; Bs[lk + 1][lr + 64] = b1.y;
        Bs[lk + 2][lr + 64] = b1.z; Bs[lk + 3][lr + 64] = b1.w;

        __syncthreads();
#pragma unroll
        for (int k = 0; k < BK; k++) {
            float4 av0 = *(const float4*)&As[k][ty * 8];
            float4 av1 = *(const float4*)&As[k][ty * 8 + 4];
            float4 bv0 = *(const float4*)&Bs[k][tx * 8];
            float4 bv1 = *(const float4*)&Bs[k][tx * 8 + 4];
            float a[8] = {av0.x, av0.y, av0.z, av0.w, av1.x, av1.y, av1.z, av1.w};
            float b[8] = {bv0.x, bv0.y, bv0.z, bv0.w, bv1.x, bv1.y, bv1.z, bv1.w};
#pragma unroll
            for (int i = 0; i < 8; i++)
#pragma unroll
                for (int j = 0; j < 8; j++)
                    acc[i][j] = fmaf(a[i], b[j], acc[i][j]);
        }
        __syncthreads();
    }

    // ---- epilogue: bias, q-scale, RoPE, store to [n][h][d] ----
    const float rscale = (mode == 0) ? 0.08838834764831845f : 1.0f;  // 1/sqrt(128)
    float bcol[8];
#pragma unroll
    for (int j = 0; j < 8; j++) {
        int jg = n0 + tx * 8 + j;
        bcol[j] = bias[((jg & 127) << 2) + (jg >> 7)];
    }
    const int dbase = (n0 + tx * 8) & 127;   // d within head; even, 8-aligned

#pragma unroll
    for (int i = 0; i < 8; i++) {
        int gm = m0 + ty * 8 + i;
        if (gm >= N_NODES) continue;
        float v[8];
#pragma unroll
        for (int j = 0; j < 8; j++) v[j] = (acc[i][j] + bcol[j]) * rscale;

        if (mode != 2) {  // RoPE for q and k
            float p0 = pos[gm * 3 + 0];
            float p1 = pos[gm * 3 + 1];
            float p2 = pos[gm * 3 + 2];
#pragma unroll
            for (int pr = 0; pr < 4; pr++) {
                int d = dbase + pr * 2;
                if (d < D_ROPE) {
                    int pp = d / 42;
                    int mi = (d - pp * 42) >> 1;
                    float ps = (pp == 0) ? p0 : (pp == 1 ? p1 : p2);
                    float ang = ps * rope_inv_freq(mi);
                    float sn, cs;
                    rope_sincos(ang, sn, cs);
                    float ev = v[pr * 2], od = v[pr * 2 + 1];
                    v[pr * 2]     = ev * cs - od * sn;
                    v[pr * 2 + 1] = ev * sn + od * cs;
                }
            }
        }
        float4* o = (float4*)(out + (size_t)gm * OUT_DIM + n0 + tx * 8);
        o[0] = make_float4(v[0], v[1], v[2], v[3]);
        o[1] = make_float4(v[4], v[5], v[6], v[7]);
    }
}

// ---------------- per-node 16-edge softmax attention -------------------------
// block = node, warp = head, lane = 4 consecutive d's (float4)
__global__ __launch_bounds__(128)
void attn_kernel(const int* __restrict__ cols) {
    const int i    = blockIdx.x;
    const int h    = threadIdx.x >> 5;
    const int lane = threadIdx.x & 31;

    __shared__ int scol[DEG];
    if (threadIdx.x < DEG) scol[threadIdx.x] = cols[i * DEG + threadIdx.x];
    __syncthreads();

    const int off = i * OUT_DIM + h * DH + lane * 4;
    const float4 q4 = *(const float4*)(g_q + off);

    float sc = -1e30f;
#pragma unroll
    for (int e = 0; e < DEG; e++) {
        int c = scol[e];
        float4 k4 = *(const float4*)(g_k + c * OUT_DIM + h * DH + lane * 4);
        float s = q4.x * k4.x;
        s = fmaf(q4.y, k4.y, s);
        s = fmaf(q4.z, k4.z, s);
        s = fmaf(q4.w, k4.w, s);
        s += __shfl_xor_sync(0xffffffffu, s, 16);
        s += __shfl_xor_sync(0xffffffffu, s, 8);
        s += __shfl_xor_sync(0xffffffffu, s, 4);
        s += __shfl_xor_sync(0xffffffffu, s, 2);
        s += __shfl_xor_sync(0xffffffffu, s, 1);
        if (lane == e) sc = s;   // lanes 0..15 hold the 16 scores
    }

    float mx = sc;
    mx = fmaxf(mx, __shfl_xor_sync(0xffffffffu, mx, 8));
    mx = fmaxf(mx, __shfl_xor_sync(0xffffffffu, mx, 4));
    mx = fmaxf(mx, __shfl_xor_sync(0xffffffffu, mx, 2));
    mx = fmaxf(mx, __shfl_xor_sync(0xffffffffu, mx, 1));

    float p = expf(sc - mx);
    float denom = p;
    denom += __shfl_xor_sync(0xffffffffu, denom, 8);
    denom += __shfl_xor_sync(0xffffffffu, denom, 4);
    denom += __shfl_xor_sync(0xffffffffu, denom, 2);
    denom += __shfl_xor_sync(0xffffffffu, denom, 1);
    float attn = p / denom;

    float4 acc = make_float4(0.f, 0.f, 0.f, 0.f);
#pragma unroll
    for (int e = 0; e < DEG; e++) {
        int c = scol[e];
        float pe = __shfl_sync(0xffffffffu, attn, e);
        float4 v4 = *(const float4*)(g_v + c * OUT_DIM + h * DH + lane * 4);
        acc.x = fmaf(pe, v4.x, acc.x);
        acc.y = fmaf(pe, v4.y, acc.y);
        acc.z = fmaf(pe, v4.z, acc.z);
        acc.w = fmaf(pe, v4.w, acc.w);
    }
    *(float4*)(g_y + off) = acc;
}

// ---------------- output projection GEMM -------------------------------------
// out[m,o] = sum_j g_y[m,j] * g_WoP[o,j] + bo[o]
__global__ __launch_bounds__(256, 2)
void out_gemm_kernel(const float* __restrict__ bo, float* __restrict__ out)
{
    __shared__ float As[BK][BM + 4];
    __shared__ float Bs[BK][BN + 4];

    const int tid = threadIdx.x;
    const int m0 = blockIdx.x * BM;
    const int n0 = blockIdx.y * BN;

    const int lr = tid >> 2;
    const int lk = (tid & 3) << 2;

    const int gm0 = m0 + lr;
    const int gm1 = m0 + lr + 64;

    const float* Wrow0 = g_WoP + (size_t)(n0 + lr) * OUT_DIM;
    const float* Wrow1 = g_WoP + (size_t)(n0 + lr + 64) * OUT_DIM;

    const int ty = tid >> 4;
    const int tx = tid & 15;

    float acc[8][8];
#pragma unroll
    for (int i = 0; i < 8; i++)
#pragma unroll
        for (int j = 0; j < 8; j++) acc[i][j] = 0.f;

    for (int k0 = 0; k0 < OUT_DIM; k0 += BK) {
        float4 a0 = (gm0 < N_NODES) ? *(const float4*)(g_y + (size_t)gm0 * OUT_DIM + k0 + lk)
                                    : make_float4(0.f, 0.f, 0.f, 0.f);
        float4 a1 = (gm1 < N_NODES) ? *(const float4*)(g_y + (size_t)gm1 * OUT_DIM + k0 + lk)
                                    : make_float4(0.f, 0.f, 0.f, 0.f);
        float4 b0 = *(const float4*)(Wrow0 + k0 + lk);
        float4 b1 = *(const float4*)(Wrow1 + k0 + lk);

        As[lk + 0][lr] = a0.x; As[lk + 1][lr] = a0.y;
        As[lk + 2][lr] = a0.z; As[lk + 3][lr] = a0.w;
        As[lk + 0][lr + 64] = a1.x; As[lk + 1][lr + 64] = a1.y;
        As[lk + 2][lr + 64] = a1.z; As[lk + 3][lr + 64] = a1.w;

        Bs[lk + 0][lr] = b0.x; Bs[lk + 1][lr] = b0.y;
        Bs[lk + 2][lr] = b0.z; Bs[lk + 3][lr] = b0.w;
        Bs[lk + 0][lr + 64] = b1.x; Bs[lk + 1][lr + 64] = b1.y;
        Bs[lk + 2][lr + 64] = b1.z; Bs[lk + 3][lr + 64] = b1.w;

        __syncthreads();
#pragma unroll
        for (int k = 0; k < BK; k++) {
            float4 av0 = *(const float4*)&As[k][ty * 8];
            float4 av1 = *(const float4*)&As[k][ty * 8 + 4];
            float4 bv0 = *(const float4*)&Bs[k][tx * 8];
            float4 bv1 = *(const float4*)&Bs[k][tx * 8 + 4];
            float a[8] = {av0.x, av0.y, av0.z, av0.w, av1.x, av1.y, av1.z, av1.w};
            float b[8] = {bv0.x, bv0.y, bv0.z, bv0.w, bv1.x, bv1.y, bv1.z, bv1.w};
#pragma unroll
            for (int i = 0; i < 8; i++)
#pragma unroll
                for (int j = 0; j < 8; j++)
                    acc[i][j] = fmaf(a[i], b[j], acc[i][j]);
        }
        __syncthreads();
    }

    float bcol[8];
#pragma unroll
    for (int j = 0; j < 8; j++) bcol[j] = bo[n0 + tx * 8 + j];

#pragma unroll
    for (int i = 0; i < 8; i++) {
        int gm = m0 + ty * 8 + i;
        if (gm >= N_NODES) continue;
        float4 o0 = make_float4(acc[i][0] + bcol[0], acc[i][1] + bcol[1],
                                acc[i][2] + bcol[2], acc[i][3] + bcol[3]);
        float4 o1 = make_float4(acc[i][4] + bcol[4], acc[i][5] + bcol[5],
                                acc[i][6] + bcol[6], acc[i][7] + bcol[7]);
        float4* o = (float4*)(out + (size_t)gm * OUT_DIM + n0 + tx * 8);
        o[0] = o0;
        o[1] = o1;
    }
}

// -----------------------------------------------------------------------------
extern "C" void kernel_launch(void* const* d_in, const int* in_sizes, int n_in,
                              void* d_out, int out_size) {
    const float* x   = (const float*)d_in[0];
    const float* pos = (const float*)d_in[1];
    // d_in[2] = rows (structure is implicit: node i owns edges [16i, 16i+16))
    const int*   cols = (const int*)d_in[3];
    const float* Wq = (const float*)d_in[4];
    const float* bq = (const float*)d_in[5];
    const float* Wk = (const float*)d_in[6];
    const float* bk = (const float*)d_in[7];
    const float* Wv = (const float*)d_in[8];
    const float* bv = (const float*)d_in[9];
    const float* Wo = (const float*)d_in[10];
    const float* bo = (const float*)d_in[11];
    float* out = (float*)d_out;

    permute_wo_kernel<<<(OUT_DIM * OUT_DIM) / 256, 256>>>(Wo);

    dim3 g1((N_NODES + BM - 1) / BM, OUT_DIM / BN, 3);
    qkv_gemm_kernel<<<g1, 256>>>(x, pos, Wq, bq, Wk, bk, Wv, bv);

    attn_kernel<<<N_NODES, 128>>>(cols);

    dim3 g2((N_NODES + BM - 1) / BM, OUT_DIM / BN);
    out_gemm_kernel<<<g2, 256>>>(bo, out);
}

// round 5
// speedup vs baseline: 2.3133x; 2.3133x over previous
#include <cuda_runtime.h>
#include <cuda_bf16.h>
#include <cstdint>

#define N_NODES 20000
#define M_PAD   20096           // 157 * 128
#define DEG     16
#define NHEAD   4
#define DH      128
#define D_ROPE  126
#define MT      157             // m tiles of 128

// ---------------- scratch (static device globals: allocation-free) ----------
__device__ __nv_bfloat16 g_xhi[M_PAD * 512];
__device__ __nv_bfloat16 g_xlo[M_PAD * 512];
__device__ float g_q[N_NODES * 512];
__device__ float g_k[N_NODES * 512];
__device__ float g_v[N_NODES * 512];
__device__ __nv_bfloat16 g_yhi[M_PAD * 512];   // pad rows stay zero (zero-init, never written)
__device__ __nv_bfloat16 g_ylo[M_PAD * 512];
__device__ __nv_bfloat16 g_whi[3 * 512 * 512]; // Wq/Wk/Wv rows permuted to head-major
__device__ __nv_bfloat16 g_wlo[3 * 512 * 512];
__device__ __nv_bfloat16 g_wohi[512 * 512];    // Wo cols permuted to head-major
__device__ __nv_bfloat16 g_wolo[512 * 512];

// ===================== PTX helpers (plain sm_103 features only) ==============
__device__ __forceinline__ uint32_t smem_to_u32(const void* p) {
    uint32_t a;
    asm("{ .reg .u64 t; cvta.to.shared.u64 t, %1; cvt.u32.u64 %0, t; }" : "=r"(a) : "l"(p));
    return a;
}
#define CP_ASYNC16(dst, src) \
    asm volatile("cp.async.cg.shared.global [%0], [%1], 16;" \
        :: "r"(dst), "l"(src) : "memory")
#define CP_COMMIT() asm volatile("cp.async.commit_group;" ::: "memory")
#define CP_WAIT(n)  asm volatile("cp.async.wait_group %0;" :: "n"(n) : "memory")

#define LDSM_X4(R, addr) \
    asm volatile("ldmatrix.sync.aligned.m8n8.x4.shared.b16 {%0,%1,%2,%3}, [%4];" \
        : "=r"((R)[0]), "=r"((R)[1]), "=r"((R)[2]), "=r"((R)[3]) : "r"(addr))

__device__ __forceinline__ void mma16816(float c[4], const uint32_t a[4],
                                         uint32_t b0, uint32_t b1) {
    asm volatile(
        "mma.sync.aligned.m16n8k16.row.col.f32.bf16.bf16.f32 "
        "{%0,%1,%2,%3}, {%4,%5,%6,%7}, {%8,%9}, {%0,%1,%2,%3};"
        : "+f"(c[0]), "+f"(c[1]), "+f"(c[2]), "+f"(c[3])
        : "r"(a[0]), "r"(a[1]), "r"(a[2]), "r"(a[3]), "r"(b0), "r"(b1));
}

// ---------------- accurate sincos for |a| <~ 200 (fast-math safe) -----------
__device__ __forceinline__ void rope_sincos(float a, float& s_out, float& c_out) {
    float j = rintf(a * 0.6366197723675814f);
    int   q = (int)j;
    float r = fmaf(j, -1.5703125f, a);
    r = fmaf(j, -4.837512969970703125e-4f, r);
    r = fmaf(j, -7.549789948768648e-8f, r);
    float r2 = r * r;
    float ss = -1.9515295891e-4f;
    ss = fmaf(ss, r2, 8.3321608736e-3f);
    ss = fmaf(ss, r2, -1.6666654611e-1f);
    ss = fmaf(ss * r2, r, r);
    float cc = 2.443315711809948e-5f;
    cc = fmaf(cc, r2, -1.388731625493765e-3f);
    cc = fmaf(cc, r2, 4.166664568298827e-2f);
    cc = fmaf(cc, r2, -0.5f);
    cc = fmaf(cc, r2, 1.0f);
    int qq = q & 3;
    float sv = (qq & 1) ? cc : ss;
    float cv = (qq & 1) ? ss : cc;
    if (qq & 2)       sv = -sv;
    if ((qq + 1) & 2) cv = -cv;
    s_out = sv; c_out = cv;
}
__device__ __forceinline__ float rope_inv_freq(int m) {
    return expf(-0.43858763676075163f * (float)m);   // exp(-m*ln(1e4)/21)
}
__device__ __forceinline__ void bf_split(float f, __nv_bfloat16& h, __nv_bfloat16& l) {
    h = __float2bfloat16(f);
    l = __float2bfloat16(f - __bfloat162float(h));
}

// ---------------- conversion kernels -----------------------------------------
__global__ void conv_x_kernel(const float* __restrict__ x) {
    int idx = blockIdx.x * 256 + threadIdx.x;   // handles 4 elems
    float4 xv = ((const float4*)x)[idx];
    __nv_bfloat16 h0, h1, h2, h3, l0, l1, l2, l3;
    bf_split(xv.x, h0, l0); bf_split(xv.y, h1, l1);
    bf_split(xv.z, h2, l2); bf_split(xv.w, h3, l3);
    ((__nv_bfloat162*)g_xhi)[2 * idx]     = __halves2bfloat162(h0, h1);
    ((__nv_bfloat162*)g_xhi)[2 * idx + 1] = __halves2bfloat162(h2, h3);
    ((__nv_bfloat162*)g_xlo)[2 * idx]     = __halves2bfloat162(l0, l1);
    ((__nv_bfloat162*)g_xlo)[2 * idx + 1] = __halves2bfloat162(l2, l3);
}

__global__ void conv_w_kernel(const float* __restrict__ Wq, const float* __restrict__ Wk,
                              const float* __restrict__ Wv, const float* __restrict__ Wo) {
    int idx = blockIdx.x * 256 + threadIdx.x;   // 0 .. 512*512-1
    int mat = blockIdx.y;
    if (mat < 3) {
        const float* W = (mat == 0) ? Wq : (mat == 1 ? Wk : Wv);
        int jg = idx >> 9, k = idx & 511;
        float f = W[(((jg & 127) << 2) + (jg >> 7)) * 512 + k];
        __nv_bfloat16 h, l; bf_split(f, h, l);
        g_whi[mat * 262144 + idx] = h;
        g_wlo[mat * 262144 + idx] = l;
    } else {
        int o = idx >> 9, j = idx & 511;
        float f = Wo[o * 512 + ((j & 127) << 2) + (j >> 7)];
        __nv_bfloat16 h, l; bf_split(f, h, l);
        g_wohi[idx] = h;
        g_wolo[idx] = l;
    }
}

// ---------------- HMMA split-bf16 mainloop ------------------------------------
// smem layout: 2 stages x 4 tiles (Ahi, Alo, Bhi, Blo) x 16KB (128 rows x 128B,
// SW128-swizzled, rows hold 64 bf16 of K).
#define TILE_BYTES  16384
#define STAGE_BYTES (4 * TILE_BYTES)
#define SMEM_BYTES  (2 * STAGE_BYTES)   // 131072

__device__ __forceinline__ void load_stage(
    uint32_t smem_u32, int b,
    const __nv_bfloat16* __restrict__ ahi, const __nv_bfloat16* __restrict__ alo,
    const __nv_bfloat16* __restrict__ bhi, const __nv_bfloat16* __restrict__ blo,
    int m0, int n0, int k0, int tid)
{
    const __nv_bfloat16* src[4] = { ahi, alo, bhi, blo };
    const uint32_t buf = smem_u32 + b * STAGE_BYTES;
#pragma unroll
    for (int t = 0; t < 4; t++) {
        const __nv_bfloat16* g = src[t];
        const int r0 = (t < 2) ? m0 : n0;
        const uint32_t tb = buf + t * TILE_BYTES;
#pragma unroll
        for (int i = 0; i < 4; i++) {
            int cid = i * 256 + tid;          // 0..1023
            int row = cid >> 3, c = cid & 7;  // 128 rows x 8 chunks of 16B
            uint32_t dst = tb + row * 128 + ((c ^ (row & 7)) << 4);
            const void* s = g + (size_t)(r0 + row) * 512 + k0 + c * 8;
            CP_ASYNC16(dst, s);
        }
    }
    CP_COMMIT();
}

// acc[mi][ni][4]: warp tile 64(m) x 32(n); mi: 4 x m16, ni: 4 x n8
__device__ __forceinline__ void compute_stage(
    uint32_t buf, int lane, int wm, int wn, float acc[4][4][4])
{
    const int g = lane >> 3, r = lane & 7;
    const int a_row0 = wm * 64 + ((g & 1) << 3) + r;
    const int a_ch0  = g >> 1;
    const int b_row0 = wn * 32 + ((g >> 1) << 3) + r;
    const int b_ch0  = g & 1;

#pragma unroll
    for (int kb = 0; kb < 4; kb++) {
        uint32_t ah[4][4], al[4][4];
#pragma unroll
        for (int mi = 0; mi < 4; mi++) {
            int row = a_row0 + mi * 16;
            int ch  = 2 * kb + a_ch0;
            uint32_t off = row * 128 + ((ch ^ (row & 7)) << 4);
            LDSM_X4(ah[mi], buf + off);
            LDSM_X4(al[mi], buf + TILE_BYTES + off);
        }
        uint32_t bh[2][4], bl[2][4];   // [nb][4]: regs {0,1}=frag 2nb, {2,3}=frag 2nb+1
#pragma unroll
        for (int nb = 0; nb < 2; nb++) {
            int row = b_row0 + nb * 16;
            int ch  = 2 * kb + b_ch0;
            uint32_t off = row * 128 + ((ch ^ (row & 7)) << 4);
            LDSM_X4(bh[nb], buf + 2 * TILE_BYTES + off);
            LDSM_X4(bl[nb], buf + 3 * TILE_BYTES + off);
        }
#pragma unroll
        for (int mi = 0; mi < 4; mi++) {
#pragma unroll
            for (int ni = 0; ni < 4; ni++) {
                uint32_t bh0 = bh[ni >> 1][(ni & 1) * 2], bh1 = bh[ni >> 1][(ni & 1) * 2 + 1];
                uint32_t bl0 = bl[ni >> 1][(ni & 1) * 2], bl1 = bl[ni >> 1][(ni & 1) * 2 + 1];
                mma16816(acc[mi][ni], ah[mi], bh0, bh1);   // hi*hi
                mma16816(acc[mi][ni], ah[mi], bl0, bl1);   // hi*lo
                mma16816(acc[mi][ni], al[mi], bh0, bh1);   // lo*hi
            }
        }
    }
}

__device__ __forceinline__ void gemm_mainloop(
    const __nv_bfloat16* __restrict__ ahi, const __nv_bfloat16* __restrict__ alo,
    const __nv_bfloat16* __restrict__ bhi, const __nv_bfloat16* __restrict__ blo,
    int m0, int n0, uint32_t smem_u32, int tid, int lane, int wm, int wn,
    float acc[4][4][4])
{
#pragma unroll
    for (int mi = 0; mi < 4; mi++)
#pragma unroll
        for (int ni = 0; ni < 4; ni++)
#pragma unroll
            for (int q = 0; q < 4; q++) acc[mi][ni][q] = 0.f;

    load_stage(smem_u32, 0, ahi, alo, bhi, blo, m0, n0, 0, tid);
#pragma unroll 1
    for (int s = 0; s < 8; s++) {
        if (s < 7)
            load_stage(smem_u32, (s + 1) & 1, ahi, alo, bhi, blo, m0, n0, (s + 1) * 64, tid);
        if (s < 7) { CP_WAIT(1); } else { CP_WAIT(0); }
        __syncthreads();
        compute_stage(smem_u32 + (s & 1) * STAGE_BYTES, lane, wm, wn, acc);
        __syncthreads();
    }
}

// ---------------- QKV GEMM (+bias, +q-scale, +RoPE) ---------------------------
__global__ __launch_bounds__(256, 1)
void qkv_tc_kernel(const float* __restrict__ pos,
                   const float* __restrict__ bq, const float* __restrict__ bk,
                   const float* __restrict__ bv)
{
    extern __shared__ __align__(1024) char smem[];
    const uint32_t smem_u32 = smem_to_u32(smem);
    const int tid  = threadIdx.x;
    const int lane = tid & 31;
    const int w    = tid >> 5;
    const int wm   = w & 1, wn = w >> 1;
    const int m0   = blockIdx.x * 128;
    const int head = blockIdx.y;
    const int mode = blockIdx.z;     // 0=q, 1=k, 2=v

    const __nv_bfloat16* bh = g_whi + (size_t)mode * 262144 + (size_t)head * 128 * 512;
    const __nv_bfloat16* bl = g_wlo + (size_t)mode * 262144 + (size_t)head * 128 * 512;

    float acc[4][4][4];
    gemm_mainloop(g_xhi, g_xlo, bh, bl, m0, 0, smem_u32, tid, lane, wm, wn, acc);

    // ---- epilogue ----
    const float* bias = (mode == 0) ? bq : (mode == 1 ? bk : bv);
    const float rs = (mode == 0) ? 0.08838834764831845f : 1.0f;   // 1/sqrt(128)
    float* outp = (mode == 0) ? g_q : (mode == 1 ? g_k : g_v);
    const int tg = lane >> 2, tq = lane & 3;

#pragma unroll
    for (int mi = 0; mi < 4; mi++) {
#pragma unroll
        for (int half = 0; half < 2; half++) {
            int row = m0 + wm * 64 + mi * 16 + half * 8 + tg;
            if (row >= N_NODES) continue;
            float p0 = 0.f, p1 = 0.f, p2 = 0.f;
            if (mode != 2) {
                p0 = pos[row * 3 + 0]; p1 = pos[row * 3 + 1]; p2 = pos[row * 3 + 2];
            }
#pragma unroll
            for (int ni = 0; ni < 4; ni++) {
                int d = wn * 32 + ni * 8 + tq * 2;
                float v0 = (acc[mi][ni][half * 2 + 0] + __ldg(&bias[d * 4 + head])) * rs;
                float v1 = (acc[mi][ni][half * 2 + 1] + __ldg(&bias[(d + 1) * 4 + head])) * rs;
                if (mode != 2 && d < D_ROPE) {
                    int pp = (d >= 84) ? 2 : ((d >= 42) ? 1 : 0);
                    int mf = (d - pp * 42) >> 1;
                    float ps = (pp == 0) ? p0 : (pp == 1 ? p1 : p2);
                    float ang = ps * rope_inv_freq(mf);
                    float sn, cs;
                    rope_sincos(ang, sn, cs);
                    float ev = v0, od = v1;
                    v0 = ev * cs - od * sn;
                    v1 = ev * sn + od * cs;
                }
                *(float2*)(outp + (size_t)row * 512 + head * DH + d) = make_float2(v0, v1);
            }
        }
    }
}

// ---------------- output projection GEMM --------------------------------------
__global__ __launch_bounds__(256, 1)
void out_tc_kernel(const float* __restrict__ bo, float* __restrict__ out)
{
    extern __shared__ __align__(1024) char smem[];
    const uint32_t smem_u32 = smem_to_u32(smem);
    const int tid  = threadIdx.x;
    const int lane = tid & 31;
    const int w    = tid >> 5;
    const int wm   = w & 1, wn = w >> 1;
    const int m0   = blockIdx.x * 128;
    const int n0   = blockIdx.y * 128;

    const __nv_bfloat16* bh = g_wohi + (size_t)n0 * 512;
    const __nv_bfloat16* bl = g_wolo + (size_t)n0 * 512;

    float acc[4][4][4];
    gemm_mainloop(g_yhi, g_ylo, bh, bl, m0, 0, smem_u32, tid, lane, wm, wn, acc);

    const int tg = lane >> 2, tq = lane & 3;
#pragma unroll
    for (int mi = 0; mi < 4; mi++) {
#pragma unroll
        for (int half = 0; half < 2; half++) {
            int row = m0 + wm * 64 + mi * 16 + half * 8 + tg;
            if (row >= N_NODES) continue;
#pragma unroll
            for (int ni = 0; ni < 4; ni++) {
                int d = wn * 32 + ni * 8 + tq * 2;
                float v0 = acc[mi][ni][half * 2 + 0] + __ldg(&bo[n0 + d]);
                float v1 = acc[mi][ni][half * 2 + 1] + __ldg(&bo[n0 + d + 1]);
                *(float2*)(out + (size_t)row * 512 + n0 + d) = make_float2(v0, v1);
            }
        }
    }
}

// ---------------- per-node 16-edge softmax attention --------------------------
__global__ __launch_bounds__(128)
void attn_kernel(const int* __restrict__ cols) {
    const int i    = blockIdx.x;
    const int hh   = threadIdx.x >> 5;
    const int lane = threadIdx.x & 31;

    __shared__ int scol[DEG];
    if (threadIdx.x < DEG) scol[threadIdx.x] = cols[i * DEG + threadIdx.x];
    __syncthreads();

    const int off = i * 512 + hh * DH + lane * 4;
    const float4 q4 = *(const float4*)(g_q + off);

    float sc = -1e30f;
#pragma unroll
    for (int e = 0; e < DEG; e++) {
        int c = scol[e];
        float4 k4 = *(const float4*)(g_k + c * 512 + hh * DH + lane * 4);
        float s = q4.x * k4.x;
        s = fmaf(q4.y, k4.y, s);
        s = fmaf(q4.z, k4.z, s);
        s = fmaf(q4.w, k4.w, s);
        s += __shfl_xor_sync(0xffffffffu, s, 16);
        s += __shfl_xor_sync(0xffffffffu, s, 8);
        s += __shfl_xor_sync(0xffffffffu, s, 4);
        s += __shfl_xor_sync(0xffffffffu, s, 2);
        s += __shfl_xor_sync(0xffffffffu, s, 1);
        if (lane == e) sc = s;
    }

    float mx = sc;
    mx = fmaxf(mx, __shfl_xor_sync(0xffffffffu, mx, 8));
    mx = fmaxf(mx, __shfl_xor_sync(0xffffffffu, mx, 4));
    mx = fmaxf(mx, __shfl_xor_sync(0xffffffffu, mx, 2));
    mx = fmaxf(mx, __shfl_xor_sync(0xffffffffu, mx, 1));

    float p = expf(sc - mx);
    float denom = p;
    denom += __shfl_xor_sync(0xffffffffu, denom, 8);
    denom += __shfl_xor_sync(0xffffffffu, denom, 4);
    denom += __shfl_xor_sync(0xffffffffu, denom, 2);
    denom += __shfl_xor_sync(0xffffffffu, denom, 1);
    float attn = p / denom;

    float4 acc = make_float4(0.f, 0.f, 0.f, 0.f);
#pragma unroll
    for (int e = 0; e < DEG; e++) {
        int c = scol[e];
        float pe = __shfl_sync(0xffffffffu, attn, e);
        float4 v4 = *(const float4*)(g_v + c * 512 + hh * DH + lane * 4);
        acc.x = fmaf(pe, v4.x, acc.x);
        acc.y = fmaf(pe, v4.y, acc.y);
        acc.z = fmaf(pe, v4.z, acc.z);
        acc.w = fmaf(pe, v4.w, acc.w);
    }

    // split-bf16 store of y for the output projection
    __nv_bfloat16 h0, h1, h2, h3, l0, l1, l2, l3;
    bf_split(acc.x, h0, l0); bf_split(acc.y, h1, l1);
    bf_split(acc.z, h2, l2); bf_split(acc.w, h3, l3);
    __nv_bfloat162* yh = (__nv_bfloat162*)(g_yhi + off);
    __nv_bfloat162* yl = (__nv_bfloat162*)(g_ylo + off);
    yh[0] = __halves2bfloat162(h0, h1);
    yh[1] = __halves2bfloat162(h2, h3);
    yl[0] = __halves2bfloat162(l0, l1);
    yl[1] = __halves2bfloat162(l2, l3);
}

// -----------------------------------------------------------------------------
extern "C" void kernel_launch(void* const* d_in, const int* in_sizes, int n_in,
                              void* d_out, int out_size) {
    const float* x   = (const float*)d_in[0];
    const float* pos = (const float*)d_in[1];
    // d_in[2] = rows (implicit: node i owns edges [16i, 16i+16))
    const int*   cols = (const int*)d_in[3];
    const float* Wq = (const float*)d_in[4];
    const float* bq = (const float*)d_in[5];
    const float* Wk = (const float*)d_in[6];
    const float* bk = (const float*)d_in[7];
    const float* Wv = (const float*)d_in[8];
    const float* bv = (const float*)d_in[9];
    const float* Wo = (const float*)d_in[10];
    const float* bo = (const float*)d_in[11];
    float* out = (float*)d_out;

    static bool attr_set = false;
    if (!attr_set) {
        cudaFuncSetAttribute(qkv_tc_kernel, cudaFuncAttributeMaxDynamicSharedMemorySize, SMEM_BYTES);
        cudaFuncSetAttribute(out_tc_kernel, cudaFuncAttributeMaxDynamicSharedMemorySize, SMEM_BYTES);
        attr_set = true;
    }

    conv_x_kernel<<<(N_NODES * 512 / 4) / 256, 256>>>(x);
    conv_w_kernel<<<dim3(512 * 512 / 256, 4), 256>>>(Wq, Wk, Wv, Wo);

    qkv_tc_kernel<<<dim3(MT, NHEAD, 3), 256, SMEM_BYTES>>>(pos, bq, bk, bv);

    attn_kernel<<<N_NODES, 128>>>(cols);

    out_tc_kernel<<<dim3(MT, NHEAD), 256, SMEM_BYTES>>>(bo, out);
}